// round 8
// baseline (speedup 1.0000x reference)
#include <cuda_runtime.h>
#include <cuda_fp16.h>

#define NB 16
#define NP 2048
#define NSEG 4
#define SEGLEN (NP / NSEG)          // 512
#define INV_N (1.0f/2048.0f)
#define REG 1e-8f

// Static device scratch (no cudaMalloc allowed).
__device__ __half g_Kh[(size_t)NB * NP * NP]; // row-scaled kernel matrix, 128 MB
__device__ float  g_RS[NB * NP];              // per-row max of K (scale factor)
__device__ float  g_U[NB * NP];
__device__ float  g_P[NB * NSEG * NP];        // ktu partial sums per n-segment

// ---------------------------------------------------------------------------
// Init: u0 = 1/N everywhere, zero the output scalar.
// ---------------------------------------------------------------------------
__global__ void init_kernel(float* out) {
    int i = blockIdx.x * blockDim.x + threadIdx.x;
    if (i < NB * NP) g_U[i] = INV_N;
    if (i == 0) out[0] = 0.0f;
}

// ---------------------------------------------------------------------------
// Build Ks[b][n][m] = K/rowmax in fp16, rowmax in g_RS.
// K[b][n][m] = exp(-10 * ||x_bn - y_bm||^2). One 256-thr block per (b, n) row;
// each thread keeps its 8 exp values in registers, block-reduce the max,
// then store scaled fp16.  x, y layout: (B, 3, N) -> x[(b*3+d)*NP + n]
// ---------------------------------------------------------------------------
__global__ void build_kernel(const float* __restrict__ x,
                             const float* __restrict__ y) {
    int n = blockIdx.x;
    int b = blockIdx.y;
    const float* xb = x + (size_t)b * 3 * NP;
    const float* yb = y + (size_t)b * 3 * NP;
    float x0 = xb[n], x1 = xb[NP + n], x2 = xb[2 * NP + n];

    float k[8];
    float mx = 0.0f;
    #pragma unroll
    for (int i = 0; i < 8; ++i) {
        int m = threadIdx.x + i * 256;
        float d0 = x0 - yb[m];
        float d1 = x1 - yb[NP + m];
        float d2 = x2 - yb[2 * NP + m];
        float c = d0 * d0 + d1 * d1 + d2 * d2;   // >= 0 by construction
        k[i] = __expf(-10.0f * c);
        mx = fmaxf(mx, k[i]);
    }

    __shared__ float red[256];
    red[threadIdx.x] = mx;
    __syncthreads();
    #pragma unroll
    for (int off = 128; off; off >>= 1) {
        if (threadIdx.x < off)
            red[threadIdx.x] = fmaxf(red[threadIdx.x], red[threadIdx.x + off]);
        __syncthreads();
    }
    float rowmax = red[0];
    float inv = (rowmax > 0.0f) ? (1.0f / rowmax) : 0.0f;

    __half* Krow = g_Kh + ((size_t)(b * NP + n)) * NP;
    #pragma unroll
    for (int i = 0; i < 8; ++i)
        Krow[threadIdx.x + i * 256] = __float2half_rn(k[i] * inv);

    if (threadIdx.x == 0) g_RS[b * NP + n] = rowmax;
}

// ---------------------------------------------------------------------------
// Stage 1 of V update: partial column sums over one 512-row segment.
//   g_P[b][seg][m] = sum_{n in seg} Ks_nm * (u_n * rowmax_n)
// Each thread owns 4 adjacent columns (one 8-byte K load / row, float4 store).
// grid (NP/512, NSEG, NB) = 256 CTAs, 128 threads. Unroll 16 -> ~4 KB in
// flight per warp. No atomics, no zeroing: one writer per (b,seg,m).
// ---------------------------------------------------------------------------
__global__ void ktu_partial_kernel() {
    int b = blockIdx.z;
    int seg = blockIdx.y;
    int base = seg * SEGLEN;

    __shared__ float ws[SEGLEN];   // u_n * rowmax_n for this segment
    for (int i = threadIdx.x; i < SEGLEN; i += 128)
        ws[i] = g_U[b * NP + base + i] * g_RS[b * NP + base + i];
    __syncthreads();

    int c2 = blockIdx.x * 128 + threadIdx.x;     // index in 4-column units
    const int2* Kp = (const int2*)(g_Kh + (size_t)b * NP * NP)
                     + (size_t)base * (NP / 4) + c2;

    float a0 = 0.f, a1 = 0.f, a2 = 0.f, a3 = 0.f;
    #pragma unroll 16
    for (int n = 0; n < SEGLEN; ++n) {
        int2 raw = Kp[(size_t)n * (NP / 4)];
        float2 f0 = __half22float2(*(const __half2*)&raw.x);
        float2 f1 = __half22float2(*(const __half2*)&raw.y);
        float w = ws[n];
        a0 += f0.x * w;
        a1 += f0.y * w;
        a2 += f1.x * w;
        a3 += f1.y * w;
    }
    float4 o = make_float4(a0, a1, a2, a3);
    *(float4*)(g_P + ((size_t)(b * NSEG + seg)) * NP + c2 * 4) = o;
}

// ---------------------------------------------------------------------------
// U update: u_n = inv_n / (rowmax_n * sum_m Ks_nm v_m + 1e-8), where
// v_m = inv_n / (sum_seg P[b][seg][m] + 1e-8), reduced+transformed on the fly
// while staging v into shared memory. FOUR rows per warp so one vs[] smem read
// feeds 4 rows of K (smem traffic 2 KB/row vs 4 KB global/row -> HBM-bound).
// grid (NP/32, NB) = 1024 CTAs, 256 threads (8 warps * 4 rows = 32 rows/CTA).
// ---------------------------------------------------------------------------
__global__ void kv_kernel() {
    int b = blockIdx.y;
    __shared__ __align__(16) float vs[NP];
    {
        const float* P0 = g_P + ((size_t)(b * NSEG + 0)) * NP;
        const float* P1 = g_P + ((size_t)(b * NSEG + 1)) * NP;
        const float* P2 = g_P + ((size_t)(b * NSEG + 2)) * NP;
        const float* P3 = g_P + ((size_t)(b * NSEG + 3)) * NP;
        for (int i = threadIdx.x; i < NP; i += 256) {
            float s = (P0[i] + P1[i]) + (P2[i] + P3[i]);
            vs[i] = INV_N / (s + REG);
        }
    }
    __syncthreads();

    int warp = threadIdx.x >> 5;
    int lane = threadIdx.x & 31;
    int n0 = blockIdx.x * 32 + warp * 4;
    const int4* K0 = (const int4*)(g_Kh + ((size_t)(b * NP + n0)) * NP);
    const int4* K1 = K0 + NP / 8;
    const int4* K2 = K1 + NP / 8;
    const int4* K3 = K2 + NP / 8;

    float s0 = 0.f, s1 = 0.f, s2 = 0.f, s3 = 0.f;
    #pragma unroll 2
    for (int i = lane; i < NP / 8; i += 32) {     // 8 iterations, 16B K loads
        const float4* vv = (const float4*)vs + i * 2;
        float4 va = vv[0], vb4 = vv[1];
        int4 r0 = K0[i], r1 = K1[i], r2 = K2[i], r3 = K3[i];

        #define DOT8(raw, acc) do {                                          \
            const __half2* h = (const __half2*)&(raw);                       \
            float2 f0 = __half22float2(h[0]);                                \
            float2 f1 = __half22float2(h[1]);                                \
            float2 f2 = __half22float2(h[2]);                                \
            float2 f3 = __half22float2(h[3]);                                \
            acc += f0.x * va.x + f0.y * va.y + f1.x * va.z + f1.y * va.w     \
                 + f2.x * vb4.x + f2.y * vb4.y + f3.x * vb4.z + f3.y * vb4.w;\
        } while (0)

        DOT8(r0, s0);
        DOT8(r1, s1);
        DOT8(r2, s2);
        DOT8(r3, s3);
        #undef DOT8
    }
    #pragma unroll
    for (int off = 16; off; off >>= 1) {
        s0 += __shfl_xor_sync(0xffffffffu, s0, off);
        s1 += __shfl_xor_sync(0xffffffffu, s1, off);
        s2 += __shfl_xor_sync(0xffffffffu, s2, off);
        s3 += __shfl_xor_sync(0xffffffffu, s3, off);
    }
    if (lane == 0) {
        g_U[b * NP + n0 + 0] = INV_N / (g_RS[b * NP + n0 + 0] * s0 + REG);
        g_U[b * NP + n0 + 1] = INV_N / (g_RS[b * NP + n0 + 1] * s1 + REG);
        g_U[b * NP + n0 + 2] = INV_N / (g_RS[b * NP + n0 + 2] * s2 + REG);
        g_U[b * NP + n0 + 3] = INV_N / (g_RS[b * NP + n0 + 3] * s3 + REG);
    }
}

// ---------------------------------------------------------------------------
// out += sum_{b,n,m} u_n * K_nm * C_nm * v_m / B,  K_nm = Ks_nm * rowmax_n.
// v reconstructed from partials (same as kv); C recomputed on the fly.
// One block per (b, n) row; block reduce + atomicAdd.
// ---------------------------------------------------------------------------
__global__ void final_kernel(const float* __restrict__ x,
                             const float* __restrict__ y,
                             float* out) {
    int n = blockIdx.x;
    int b = blockIdx.y;

    __shared__ float vs[NP];
    {
        const float* P0 = g_P + ((size_t)(b * NSEG + 0)) * NP;
        const float* P1 = g_P + ((size_t)(b * NSEG + 1)) * NP;
        const float* P2 = g_P + ((size_t)(b * NSEG + 2)) * NP;
        const float* P3 = g_P + ((size_t)(b * NSEG + 3)) * NP;
        for (int i = threadIdx.x; i < NP; i += 256) {
            float s = (P0[i] + P1[i]) + (P2[i] + P3[i]);
            vs[i] = INV_N / (s + REG);
        }
    }
    __syncthreads();

    const float* xb = x + (size_t)b * 3 * NP;
    const float* yb = y + (size_t)b * 3 * NP;
    float x0 = xb[n], x1 = xb[NP + n], x2 = xb[2 * NP + n];
    const __half* Krow = g_Kh + ((size_t)(b * NP + n)) * NP;

    float s = 0.f;
    #pragma unroll
    for (int i = 0; i < 8; ++i) {
        int m = threadIdx.x + i * 256;
        float d0 = x0 - yb[m];
        float d1 = x1 - yb[NP + m];
        float d2 = x2 - yb[2 * NP + m];
        float c = d0 * d0 + d1 * d1 + d2 * d2;
        s += __half2float(Krow[m]) * c * vs[m];
    }

    __shared__ float red[256];
    red[threadIdx.x] = s;
    __syncthreads();
    #pragma unroll
    for (int off = 128; off; off >>= 1) {
        if (threadIdx.x < off) red[threadIdx.x] += red[threadIdx.x + off];
        __syncthreads();
    }
    if (threadIdx.x == 0) {
        float rowmax = g_RS[b * NP + n];
        atomicAdd(out, red[0] * rowmax * g_U[b * NP + n] * (1.0f / NB));
    }
}

// ---------------------------------------------------------------------------
extern "C" void kernel_launch(void* const* d_in, const int* in_sizes, int n_in,
                              void* d_out, int out_size) {
    const float* x = (const float*)d_in[0];
    const float* y = (const float*)d_in[1];
    float* out = (float*)d_out;

    init_kernel<<<(NB * NP + 255) / 256, 256>>>(out);
    build_kernel<<<dim3(NP, NB), 256>>>(x, y);
    for (int it = 0; it < 100; ++it) {
        ktu_partial_kernel<<<dim3(NP / 512, NSEG, NB), 128>>>();
        kv_kernel<<<dim3(NP / 32, NB), 256>>>();
    }
    final_kernel<<<dim3(NP, NB), 256>>>(x, y, out);
}

// round 10
// speedup vs baseline: 1.6384x; 1.6384x over previous
#include <cuda_runtime.h>
#include <cuda_fp16.h>

#define NB 16
#define NP 2048
#define NSEG 8
#define SEGLEN (NP / NSEG)          // 256
#define INV_N (1.0f/2048.0f)
#define REG 1e-8f

// Static device scratch (no cudaMalloc allowed).
__device__ __half g_Kh[(size_t)NB * NP * NP]; // row-scaled kernel matrix, 128 MB
__device__ float  g_RS[NB * NP];              // per-row max of K (scale factor)
__device__ float  g_U[NB * NP];
__device__ float  g_P[NB * NSEG * NP];        // ktu partial sums per n-segment

// ---------------------------------------------------------------------------
// Init: u0 = 1/N everywhere, zero the output scalar.
// ---------------------------------------------------------------------------
__global__ void init_kernel(float* out) {
    int i = blockIdx.x * blockDim.x + threadIdx.x;
    if (i < NB * NP) g_U[i] = INV_N;
    if (i == 0) out[0] = 0.0f;
}

// ---------------------------------------------------------------------------
// Build Ks[b][n][m] = K/rowmax in fp16, rowmax in g_RS.
// K[b][n][m] = exp(-10 * ||x_bn - y_bm||^2). One 256-thr block per (b, n) row.
// x, y layout: (B, 3, N) -> x[(b*3+d)*NP + n]
// ---------------------------------------------------------------------------
__global__ void build_kernel(const float* __restrict__ x,
                             const float* __restrict__ y) {
    int n = blockIdx.x;
    int b = blockIdx.y;
    const float* xb = x + (size_t)b * 3 * NP;
    const float* yb = y + (size_t)b * 3 * NP;
    float x0 = xb[n], x1 = xb[NP + n], x2 = xb[2 * NP + n];

    float k[8];
    float mx = 0.0f;
    #pragma unroll
    for (int i = 0; i < 8; ++i) {
        int m = threadIdx.x + i * 256;
        float d0 = x0 - yb[m];
        float d1 = x1 - yb[NP + m];
        float d2 = x2 - yb[2 * NP + m];
        float c = d0 * d0 + d1 * d1 + d2 * d2;   // >= 0 by construction
        k[i] = __expf(-10.0f * c);
        mx = fmaxf(mx, k[i]);
    }

    __shared__ float red[256];
    red[threadIdx.x] = mx;
    __syncthreads();
    #pragma unroll
    for (int off = 128; off; off >>= 1) {
        if (threadIdx.x < off)
            red[threadIdx.x] = fmaxf(red[threadIdx.x], red[threadIdx.x + off]);
        __syncthreads();
    }
    float rowmax = red[0];
    float inv = (rowmax > 0.0f) ? (1.0f / rowmax) : 0.0f;

    __half* Krow = g_Kh + ((size_t)(b * NP + n)) * NP;
    #pragma unroll
    for (int i = 0; i < 8; ++i)
        Krow[threadIdx.x + i * 256] = __float2half_rn(k[i] * inv);

    if (threadIdx.x == 0) g_RS[b * NP + n] = rowmax;
}

// ---------------------------------------------------------------------------
// Stage 1 of V update: partial column sums over one 256-row segment.
//   g_P[b][seg][m] = sum_{n in seg} Ks_nm * (u_n * rowmax_n)
// Each thread owns 4 adjacent columns (one 8-byte K load / row, float4 store).
// grid (4, NSEG, NB) = 512 CTAs, 128 threads -> single balanced wave,
// ~14 warps/SM, unroll 16 -> ~55 KB in flight per SM.
// ---------------------------------------------------------------------------
__global__ void __launch_bounds__(128) ktu_partial_kernel() {
    int b = blockIdx.z;
    int seg = blockIdx.y;
    int base = seg * SEGLEN;

    __shared__ float ws[SEGLEN];   // u_n * rowmax_n for this segment
    for (int i = threadIdx.x; i < SEGLEN; i += 128)
        ws[i] = g_U[b * NP + base + i] * g_RS[b * NP + base + i];
    __syncthreads();

    int c2 = blockIdx.x * 128 + threadIdx.x;     // index in 4-column units
    const int2* Kp = (const int2*)(g_Kh + (size_t)b * NP * NP)
                     + (size_t)base * (NP / 4) + c2;

    float a0 = 0.f, a1 = 0.f, a2 = 0.f, a3 = 0.f;
    #pragma unroll 16
    for (int n = 0; n < SEGLEN; ++n) {
        int2 raw = Kp[(size_t)n * (NP / 4)];
        float2 f0 = __half22float2(*(const __half2*)&raw.x);
        float2 f1 = __half22float2(*(const __half2*)&raw.y);
        float w = ws[n];
        a0 += f0.x * w;
        a1 += f0.y * w;
        a2 += f1.x * w;
        a3 += f1.y * w;
    }
    float4 o = make_float4(a0, a1, a2, a3);
    *(float4*)(g_P + ((size_t)(b * NSEG + seg)) * NP + c2 * 4) = o;
}

// ---------------------------------------------------------------------------
// U update: u_n = inv_n / (rowmax_n * sum_m Ks_nm v_m + 1e-8), where
// v_m = inv_n / (sum_seg P[b][seg][m] + 1e-8), reduced+transformed on the fly
// into shared memory (one setup per CTA). Each CTA owns 64 rows of ONE batch
// (2 sequential 32-row blocks); 8 warps x 4 rows/warp per block so one vs[]
// smem read feeds 4 rows of K. grid = 512 CTAs x 256 thr -> single wave
// (3.46 CTAs/SM <= 5-CTA reg capacity), perfectly balanced.
// ---------------------------------------------------------------------------
__global__ void __launch_bounds__(256) kv_kernel() {
    int cta = blockIdx.x;            // 0..511
    int b = cta >> 5;                // 32 CTAs per batch
    int rowbase = (cta & 31) * 64;

    __shared__ __align__(16) float vs[NP];
    {
        const float* P = g_P + (size_t)b * NSEG * NP;
        for (int i = threadIdx.x; i < NP; i += 256) {
            float s = 0.f;
            #pragma unroll
            for (int sg = 0; sg < NSEG; ++sg) s += P[sg * NP + i];
            vs[i] = INV_N / (s + REG);
        }
    }
    __syncthreads();

    int warp = threadIdx.x >> 5;
    int lane = threadIdx.x & 31;

    #pragma unroll
    for (int rb = 0; rb < 2; ++rb) {
        int n0 = rowbase + rb * 32 + warp * 4;
        const int4* K0 = (const int4*)(g_Kh + ((size_t)(b * NP + n0)) * NP);
        const int4* K1 = K0 + NP / 8;
        const int4* K2 = K1 + NP / 8;
        const int4* K3 = K2 + NP / 8;

        float s0 = 0.f, s1 = 0.f, s2 = 0.f, s3 = 0.f;
        #pragma unroll 2
        for (int i = lane; i < NP / 8; i += 32) {   // 8 iterations, 16B loads
            const float4* vv = (const float4*)vs + i * 2;
            float4 va = vv[0], vb4 = vv[1];
            int4 r0 = K0[i], r1 = K1[i], r2 = K2[i], r3 = K3[i];

            #define DOT8(raw, acc) do {                                          \
                const __half2* h = (const __half2*)&(raw);                       \
                float2 f0 = __half22float2(h[0]);                                \
                float2 f1 = __half22float2(h[1]);                                \
                float2 f2 = __half22float2(h[2]);                                \
                float2 f3 = __half22float2(h[3]);                                \
                acc += f0.x * va.x + f0.y * va.y + f1.x * va.z + f1.y * va.w     \
                     + f2.x * vb4.x + f2.y * vb4.y + f3.x * vb4.z + f3.y * vb4.w;\
            } while (0)

            DOT8(r0, s0);
            DOT8(r1, s1);
            DOT8(r2, s2);
            DOT8(r3, s3);
            #undef DOT8
        }
        #pragma unroll
        for (int off = 16; off; off >>= 1) {
            s0 += __shfl_xor_sync(0xffffffffu, s0, off);
            s1 += __shfl_xor_sync(0xffffffffu, s1, off);
            s2 += __shfl_xor_sync(0xffffffffu, s2, off);
            s3 += __shfl_xor_sync(0xffffffffu, s3, off);
        }
        if (lane == 0) {
            g_U[b * NP + n0 + 0] = INV_N / (g_RS[b * NP + n0 + 0] * s0 + REG);
            g_U[b * NP + n0 + 1] = INV_N / (g_RS[b * NP + n0 + 1] * s1 + REG);
            g_U[b * NP + n0 + 2] = INV_N / (g_RS[b * NP + n0 + 2] * s2 + REG);
            g_U[b * NP + n0 + 3] = INV_N / (g_RS[b * NP + n0 + 3] * s3 + REG);
        }
    }
}

// ---------------------------------------------------------------------------
// out += sum_{b,n,m} u_n * K_nm * C_nm * v_m / B,  K_nm = Ks_nm * rowmax_n.
// v reconstructed from partials (same as kv); C recomputed on the fly.
// One block per (b, n) row; block reduce + atomicAdd.
// ---------------------------------------------------------------------------
__global__ void final_kernel(const float* __restrict__ x,
                             const float* __restrict__ y,
                             float* out) {
    int n = blockIdx.x;
    int b = blockIdx.y;

    __shared__ float vs[NP];
    {
        const float* P = g_P + (size_t)b * NSEG * NP;
        for (int i = threadIdx.x; i < NP; i += 256) {
            float s = 0.f;
            #pragma unroll
            for (int sg = 0; sg < NSEG; ++sg) s += P[sg * NP + i];
            vs[i] = INV_N / (s + REG);
        }
    }
    __syncthreads();

    const float* xb = x + (size_t)b * 3 * NP;
    const float* yb = y + (size_t)b * 3 * NP;
    float x0 = xb[n], x1 = xb[NP + n], x2 = xb[2 * NP + n];
    const __half* Krow = g_Kh + ((size_t)(b * NP + n)) * NP;

    float s = 0.f;
    #pragma unroll
    for (int i = 0; i < 8; ++i) {
        int m = threadIdx.x + i * 256;
        float d0 = x0 - yb[m];
        float d1 = x1 - yb[NP + m];
        float d2 = x2 - yb[2 * NP + m];
        float c = d0 * d0 + d1 * d1 + d2 * d2;
        s += __half2float(Krow[m]) * c * vs[m];
    }

    __shared__ float red[256];
    red[threadIdx.x] = s;
    __syncthreads();
    #pragma unroll
    for (int off = 128; off; off >>= 1) {
        if (threadIdx.x < off) red[threadIdx.x] += red[threadIdx.x + off];
        __syncthreads();
    }
    if (threadIdx.x == 0) {
        float rowmax = g_RS[b * NP + n];
        atomicAdd(out, red[0] * rowmax * g_U[b * NP + n] * (1.0f / NB));
    }
}

// ---------------------------------------------------------------------------
extern "C" void kernel_launch(void* const* d_in, const int* in_sizes, int n_in,
                              void* d_out, int out_size) {
    const float* x = (const float*)d_in[0];
    const float* y = (const float*)d_in[1];
    float* out = (float*)d_out;

    init_kernel<<<(NB * NP + 255) / 256, 256>>>(out);
    build_kernel<<<dim3(NP, NB), 256>>>(x, y);
    for (int it = 0; it < 100; ++it) {
        ktu_partial_kernel<<<dim3(4, NSEG, NB), 128>>>();
        kv_kernel<<<512, 256>>>();
    }
    final_kernel<<<dim3(NP, NB), 256>>>(x, y, out);
}

// round 16
// speedup vs baseline: 2.6657x; 1.6270x over previous
#include <cuda_runtime.h>
#include <cuda_fp16.h>

#define NB 16
#define NP 2048
#define NITER 100
#define CTAB 16                    // CTAs cooperating on one batch
#define GB 8                       // batches per L2-resident group
#define NGROUP 2
#define NCTA (CTAB * GB)           // 128 CTAs total (1 per SM, all resident)
#define THREADS 512
#define ROWS (NP / CTAB)           // 128 rows per CTA
#define INV_N (1.0f/2048.0f)
#define REG 1e-8f

// Static device scratch (no cudaMalloc allowed).
__device__ __half g_Kh[(size_t)NB * NP * NP];     // row-scaled K, fp16, 128 MB
__device__ float  g_RS[NB * NP];                  // per-row max of K
__device__ float  g_U[NB * NP];                   // u_100 (written last iter)
__device__ float  g_P[(size_t)NB * CTAB * NP];    // ktu partials, 2 MB
__device__ int    g_bar[NB * NITER * 2];          // spin-barrier counters

// ---------------------------------------------------------------------------
__global__ void init_kernel(float* out) {
    int i = blockIdx.x * blockDim.x + threadIdx.x;
    if (i < NB * NITER * 2) g_bar[i] = 0;
    if (i == 0) out[0] = 0.0f;
}

// ---------------------------------------------------------------------------
// Build Ks[b][n][m] = exp(-10*||x_bn-y_bm||^2)/rowmax in fp16; rowmax in g_RS.
// ---------------------------------------------------------------------------
__global__ void build_kernel(const float* __restrict__ x,
                             const float* __restrict__ y) {
    int n = blockIdx.x;
    int b = blockIdx.y;
    const float* xb = x + (size_t)b * 3 * NP;
    const float* yb = y + (size_t)b * 3 * NP;
    float x0 = xb[n], x1 = xb[NP + n], x2 = xb[2 * NP + n];

    float k[8];
    float mx = 0.0f;
    #pragma unroll
    for (int i = 0; i < 8; ++i) {
        int m = threadIdx.x + i * 256;
        float d0 = x0 - yb[m];
        float d1 = x1 - yb[NP + m];
        float d2 = x2 - yb[2 * NP + m];
        float c = d0 * d0 + d1 * d1 + d2 * d2;   // >= 0 by construction
        k[i] = __expf(-10.0f * c);
        mx = fmaxf(mx, k[i]);
    }

    __shared__ float red[256];
    red[threadIdx.x] = mx;
    __syncthreads();
    #pragma unroll
    for (int off = 128; off; off >>= 1) {
        if (threadIdx.x < off)
            red[threadIdx.x] = fmaxf(red[threadIdx.x], red[threadIdx.x + off]);
        __syncthreads();
    }
    float rowmax = red[0];
    float inv = (rowmax > 0.0f) ? (1.0f / rowmax) : 0.0f;

    __half* Krow = g_Kh + ((size_t)(b * NP + n)) * NP;
    #pragma unroll
    for (int i = 0; i < 8; ++i)
        Krow[threadIdx.x + i * 256] = __float2half_rn(k[i] * inv);

    if (threadIdx.x == 0) g_RS[b * NP + n] = rowmax;
}

// ---------------------------------------------------------------------------
// Spin barrier across the CTAB CTAs of one batch. All 128 CTAs are resident
// (128 <= 148 SMs) so spinning is deadlock-free. threadfence after the wait
// (gpu scope -> CCTL.IVALL) invalidates L1 so peers' fresh data is visible.
// ---------------------------------------------------------------------------
__device__ __forceinline__ void batch_barrier(int* c) {
    __threadfence();
    __syncthreads();
    if (threadIdx.x == 0) {
        atomicAdd(c, 1);
        while (*(volatile int*)c < CTAB) { }
    }
    __syncthreads();
    __threadfence();
}

// ---------------------------------------------------------------------------
// Persistent Sinkhorn: 2 groups of 8 batches; per group, the 64 MB K slice
// stays L2-resident across all 200 passes. CTA owns 128 rows of its batch.
// Per iteration:
//   A: partial column sums over own rows -> g_P        (16B loads, reg accum)
//   bar1 (P complete)
//   C-stage: v = inv_n/(sum_seg P + eps) into smem
//   bar2 (everyone past reading P, safe to overwrite next iter)
//   C: u_n = inv_n/(rs_n * sum_m Ks v + eps) for own rows, kept in smem
// ---------------------------------------------------------------------------
__global__ void __launch_bounds__(THREADS, 1) sinkhorn_kernel() {
    __shared__ __align__(16) float vs[NP];   // v vector / phase-A merge buffer
    __shared__ float ws[ROWS];               // u * rowmax for own rows
    __shared__ float u_s[ROWS];
    __shared__ float rs_s[ROWS];

    int cta = blockIdx.x;
    int bL  = cta / CTAB;
    int r   = cta % CTAB;
    int tid = threadIdx.x;
    int rowbase = r * ROWS;

    for (int g = 0; g < NGROUP; ++g) {
        int b = g * GB + bL;
        if (tid < ROWS) {
            rs_s[tid] = g_RS[b * NP + rowbase + tid];
            u_s[tid]  = INV_N;
        }
        __syncthreads();

        for (int it = 0; it < NITER; ++it) {
            if (tid < ROWS) ws[tid] = u_s[tid] * rs_s[tid];
            __syncthreads();

            // ---------------- Phase A: column partials over own 128 rows
            {
                int c8 = tid & 255;          // 8-column group
                int h  = tid >> 8;           // row half (0: rows 0-63, 1: 64-127)
                const int4* Kp = (const int4*)(g_Kh
                    + ((size_t)(b * NP + rowbase + h * 64)) * NP) + c8;
                float a0=0,a1=0,a2=0,a3=0,a4=0,a5=0,a6=0,a7=0;
                #pragma unroll 8
                for (int n = 0; n < 64; ++n) {
                    int4 raw = Kp[(size_t)n * (NP / 8)];
                    const __half2* hh = (const __half2*)&raw;
                    float w = ws[h * 64 + n];
                    float2 f0 = __half22float2(hh[0]);
                    float2 f1 = __half22float2(hh[1]);
                    float2 f2 = __half22float2(hh[2]);
                    float2 f3 = __half22float2(hh[3]);
                    a0 += f0.x * w; a1 += f0.y * w;
                    a2 += f1.x * w; a3 += f1.y * w;
                    a4 += f2.x * w; a5 += f2.y * w;
                    a6 += f3.x * w; a7 += f3.y * w;
                }
                if (h) {
                    float* pb = vs + c8 * 8;
                    pb[0]=a0; pb[1]=a1; pb[2]=a2; pb[3]=a3;
                    pb[4]=a4; pb[5]=a5; pb[6]=a6; pb[7]=a7;
                }
                __syncthreads();
                if (!h) {
                    const float* pb = vs + c8 * 8;
                    float4 o1 = make_float4(a0+pb[0], a1+pb[1], a2+pb[2], a3+pb[3]);
                    float4 o2 = make_float4(a4+pb[4], a5+pb[5], a6+pb[6], a7+pb[7]);
                    float* Pp = g_P + ((size_t)(b * CTAB + r)) * NP + c8 * 8;
                    *(float4*)Pp = o1;
                    *(float4*)(Pp + 4) = o2;
                }
            }
            batch_barrier(&g_bar[(b * NITER + it) * 2]);

            // ---------------- C-stage: reduce partials -> v into smem
            for (int i = tid; i < NP; i += THREADS) {
                float s = 0.f;
                const float* P = g_P + (size_t)b * CTAB * NP + i;
                #pragma unroll
                for (int sg = 0; sg < CTAB; ++sg) s += P[(size_t)sg * NP];
                vs[i] = INV_N / (s + REG);
            }
            batch_barrier(&g_bar[(b * NITER + it) * 2 + 1]);

            // ---------------- Phase C: u update for own rows (8 rows/warp)
            {
                int warp = tid >> 5, lane = tid & 31;
                int n0 = rowbase + warp * 8;
                const int4* Kr = (const int4*)(g_Kh + ((size_t)(b * NP + n0)) * NP);
                float acc[8] = {0,0,0,0,0,0,0,0};
                #pragma unroll
                for (int i = lane; i < NP / 8; i += 32) {
                    const float4* vv = (const float4*)vs + i * 2;
                    float4 va = vv[0], vb4 = vv[1];
                    #pragma unroll
                    for (int j = 0; j < 8; ++j) {
                        int4 raw = Kr[(size_t)j * (NP / 8) + i];
                        const __half2* hh = (const __half2*)&raw;
                        float2 f0 = __half22float2(hh[0]);
                        float2 f1 = __half22float2(hh[1]);
                        float2 f2 = __half22float2(hh[2]);
                        float2 f3 = __half22float2(hh[3]);
                        acc[j] += f0.x*va.x + f0.y*va.y + f1.x*va.z + f1.y*va.w
                                + f2.x*vb4.x + f2.y*vb4.y + f3.x*vb4.z + f3.y*vb4.w;
                    }
                }
                #pragma unroll
                for (int j = 0; j < 8; ++j) {
                    float s = acc[j];
                    #pragma unroll
                    for (int off = 16; off; off >>= 1)
                        s += __shfl_xor_sync(0xffffffffu, s, off);
                    if (lane == 0) {
                        int lrow = warp * 8 + j;
                        float un = INV_N / (rs_s[lrow] * s + REG);
                        u_s[lrow] = un;
                        if (it == NITER - 1) g_U[b * NP + rowbase + lrow] = un;
                    }
                }
            }
            __syncthreads();
        }
        __syncthreads();
    }
}

// ---------------------------------------------------------------------------
// out += sum_{b,n,m} u_n * K_nm * C_nm * v_m / B,  K_nm = Ks_nm * rowmax_n.
// v reconstructed from g_P; C recomputed on the fly.
// ---------------------------------------------------------------------------
__global__ void final_kernel(const float* __restrict__ x,
                             const float* __restrict__ y,
                             float* out) {
    int n = blockIdx.x;
    int b = blockIdx.y;

    __shared__ float vs[NP];
    for (int i = threadIdx.x; i < NP; i += 256) {
        float s = 0.f;
        const float* P = g_P + (size_t)b * CTAB * NP + i;
        #pragma unroll
        for (int sg = 0; sg < CTAB; ++sg) s += P[(size_t)sg * NP];
        vs[i] = INV_N / (s + REG);
    }
    __syncthreads();

    const float* xb = x + (size_t)b * 3 * NP;
    const float* yb = y + (size_t)b * 3 * NP;
    float x0 = xb[n], x1 = xb[NP + n], x2 = xb[2 * NP + n];
    const __half* Krow = g_Kh + ((size_t)(b * NP + n)) * NP;

    float s = 0.f;
    #pragma unroll
    for (int i = 0; i < 8; ++i) {
        int m = threadIdx.x + i * 256;
        float d0 = x0 - yb[m];
        float d1 = x1 - yb[NP + m];
        float d2 = x2 - yb[2 * NP + m];
        float c = d0 * d0 + d1 * d1 + d2 * d2;
        s += __half2float(Krow[m]) * c * vs[m];
    }

    __shared__ float red[256];
    red[threadIdx.x] = s;
    __syncthreads();
    #pragma unroll
    for (int off = 128; off; off >>= 1) {
        if (threadIdx.x < off) red[threadIdx.x] += red[threadIdx.x + off];
        __syncthreads();
    }
    if (threadIdx.x == 0) {
        float rowmax = g_RS[b * NP + n];
        atomicAdd(out, red[0] * rowmax * g_U[b * NP + n] * (1.0f / NB));
    }
}

// ---------------------------------------------------------------------------
extern "C" void kernel_launch(void* const* d_in, const int* in_sizes, int n_in,
                              void* d_out, int out_size) {
    const float* x = (const float*)d_in[0];
    const float* y = (const float*)d_in[1];
    float* out = (float*)d_out;

    init_kernel<<<(NB * NITER * 2 + 255) / 256, 256>>>(out);
    build_kernel<<<dim3(NP, NB), 256>>>(x, y);
    sinkhorn_kernel<<<NCTA, THREADS>>>();
    final_kernel<<<dim3(NP, NB), 256>>>(x, y, out);
}

// round 17
// speedup vs baseline: 2.9214x; 1.0959x over previous
#include <cuda_runtime.h>
#include <cuda_fp16.h>

#define NB 16
#define NP 2048
#define NITER 100
#define CTAB 16                    // CTAs cooperating on one batch
#define GB 8                       // batches per L2-resident group
#define NGROUP 2
#define NCTA (CTAB * GB)           // 128 CTAs total (1 per SM, all resident)
#define THREADS 512
#define ROWS (NP / CTAB)           // 128 rows per CTA
#define INV_N (1.0f/2048.0f)
#define REG 1e-8f

// Static device scratch (no cudaMalloc allowed).
__device__ __half g_Kh[(size_t)NB * NP * NP];       // row-scaled K, fp16, 128 MB
__device__ float  g_RS[NB * NP];                    // per-row max of K
__device__ float  g_U[NB * NP];                     // u_100 (written last iter)
__device__ float  g_V[NB * NP];                     // v_100 (v_finalize)
__device__ float  g_P[2][(size_t)NB * CTAB * NP];   // ktu partials, dbl-buffered
__device__ int    g_bar[NB * NITER];                // spin-barrier counters

// ---------------------------------------------------------------------------
__global__ void init_kernel(float* out) {
    int i = blockIdx.x * blockDim.x + threadIdx.x;
    if (i < NB * NITER) g_bar[i] = 0;
    if (i == 0) out[0] = 0.0f;
}

// ---------------------------------------------------------------------------
// Build Ks[b][n][m] = exp(-10*||x_bn-y_bm||^2)/rowmax in fp16; rowmax in g_RS.
// ---------------------------------------------------------------------------
__global__ void build_kernel(const float* __restrict__ x,
                             const float* __restrict__ y) {
    int n = blockIdx.x;
    int b = blockIdx.y;
    const float* xb = x + (size_t)b * 3 * NP;
    const float* yb = y + (size_t)b * 3 * NP;
    float x0 = xb[n], x1 = xb[NP + n], x2 = xb[2 * NP + n];

    float k[8];
    float mx = 0.0f;
    #pragma unroll
    for (int i = 0; i < 8; ++i) {
        int m = threadIdx.x + i * 256;
        float d0 = x0 - yb[m];
        float d1 = x1 - yb[NP + m];
        float d2 = x2 - yb[2 * NP + m];
        float c = d0 * d0 + d1 * d1 + d2 * d2;   // >= 0 by construction
        k[i] = __expf(-10.0f * c);
        mx = fmaxf(mx, k[i]);
    }

    __shared__ float red[256];
    red[threadIdx.x] = mx;
    __syncthreads();
    #pragma unroll
    for (int off = 128; off; off >>= 1) {
        if (threadIdx.x < off)
            red[threadIdx.x] = fmaxf(red[threadIdx.x], red[threadIdx.x + off]);
        __syncthreads();
    }
    float rowmax = red[0];
    float inv = (rowmax > 0.0f) ? (1.0f / rowmax) : 0.0f;

    __half* Krow = g_Kh + ((size_t)(b * NP + n)) * NP;
    #pragma unroll
    for (int i = 0; i < 8; ++i)
        Krow[threadIdx.x + i * 256] = __float2half_rn(k[i] * inv);

    if (threadIdx.x == 0) g_RS[b * NP + n] = rowmax;
}

// ---------------------------------------------------------------------------
// Spin barrier across the CTAB CTAs of one batch (all resident -> no deadlock).
// ---------------------------------------------------------------------------
__device__ __forceinline__ void batch_barrier(int* c) {
    __threadfence();
    __syncthreads();
    if (threadIdx.x == 0) {
        atomicAdd(c, 1);
        while (*(volatile int*)c < CTAB) { }
    }
    __syncthreads();
    __threadfence();
}

// ---------------------------------------------------------------------------
// Persistent Sinkhorn: 2 groups of 8 batches (64 MB K slice stays L2-resident
// across its 200 passes). ONE barrier per iteration: g_P is double-buffered by
// iteration parity, so the overwrite of parity p at iter t+2 is ordered after
// all C-stage reads of iter t by the barrier at iter t+1 (each CTA arrives
// there only after its own C-stage(t)).
// ---------------------------------------------------------------------------
__global__ void __launch_bounds__(THREADS, 1) sinkhorn_kernel() {
    __shared__ __align__(16) float vs[NP];   // v vector / phase-A merge buffer
    __shared__ float ws[ROWS];               // u * rowmax for own rows
    __shared__ float u_s[ROWS];
    __shared__ float rs_s[ROWS];

    int cta = blockIdx.x;
    int bL  = cta / CTAB;
    int r   = cta % CTAB;
    int tid = threadIdx.x;
    int rowbase = r * ROWS;

    for (int g = 0; g < NGROUP; ++g) {
        int b = g * GB + bL;
        if (tid < ROWS) {
            rs_s[tid] = g_RS[b * NP + rowbase + tid];
            u_s[tid]  = INV_N;
        }
        __syncthreads();

        for (int it = 0; it < NITER; ++it) {
            int par = it & 1;
            if (tid < ROWS) ws[tid] = u_s[tid] * rs_s[tid];
            __syncthreads();

            // ---------------- Phase A: column partials over own 128 rows
            {
                int c8 = tid & 255;          // 8-column group
                int h  = tid >> 8;           // row half (0: rows 0-63, 1: 64-127)
                const int4* Kp = (const int4*)(g_Kh
                    + ((size_t)(b * NP + rowbase + h * 64)) * NP) + c8;
                float a0=0,a1=0,a2=0,a3=0,a4=0,a5=0,a6=0,a7=0;
                #pragma unroll 8
                for (int n = 0; n < 64; ++n) {
                    int4 raw = Kp[(size_t)n * (NP / 8)];
                    const __half2* hh = (const __half2*)&raw;
                    float w = ws[h * 64 + n];
                    float2 f0 = __half22float2(hh[0]);
                    float2 f1 = __half22float2(hh[1]);
                    float2 f2 = __half22float2(hh[2]);
                    float2 f3 = __half22float2(hh[3]);
                    a0 += f0.x * w; a1 += f0.y * w;
                    a2 += f1.x * w; a3 += f1.y * w;
                    a4 += f2.x * w; a5 += f2.y * w;
                    a6 += f3.x * w; a7 += f3.y * w;
                }
                if (h) {
                    float* pb = vs + c8 * 8;
                    pb[0]=a0; pb[1]=a1; pb[2]=a2; pb[3]=a3;
                    pb[4]=a4; pb[5]=a5; pb[6]=a6; pb[7]=a7;
                }
                __syncthreads();
                if (!h) {
                    const float* pb = vs + c8 * 8;
                    float4 o1 = make_float4(a0+pb[0], a1+pb[1], a2+pb[2], a3+pb[3]);
                    float4 o2 = make_float4(a4+pb[4], a5+pb[5], a6+pb[6], a7+pb[7]);
                    float* Pp = g_P[par] + ((size_t)(b * CTAB + r)) * NP + c8 * 8;
                    *(float4*)Pp = o1;
                    *(float4*)(Pp + 4) = o2;
                }
            }
            batch_barrier(&g_bar[b * NITER + it]);

            // ---------------- C-stage: reduce partials -> v into smem
            for (int i = tid; i < NP; i += THREADS) {
                float s = 0.f;
                const float* P = g_P[par] + (size_t)b * CTAB * NP + i;
                #pragma unroll
                for (int sg = 0; sg < CTAB; ++sg) s += P[(size_t)sg * NP];
                vs[i] = INV_N / (s + REG);
            }
            __syncthreads();

            // ---------------- Phase C: u update for own rows (8 rows/warp)
            {
                int warp = tid >> 5, lane = tid & 31;
                int n0 = rowbase + warp * 8;
                const int4* Kr = (const int4*)(g_Kh + ((size_t)(b * NP + n0)) * NP);
                float acc[8] = {0,0,0,0,0,0,0,0};
                #pragma unroll
                for (int i = lane; i < NP / 8; i += 32) {
                    const float4* vv = (const float4*)vs + i * 2;
                    float4 va = vv[0], vb4 = vv[1];
                    #pragma unroll
                    for (int j = 0; j < 8; ++j) {
                        int4 raw = Kr[(size_t)j * (NP / 8) + i];
                        const __half2* hh = (const __half2*)&raw;
                        float2 f0 = __half22float2(hh[0]);
                        float2 f1 = __half22float2(hh[1]);
                        float2 f2 = __half22float2(hh[2]);
                        float2 f3 = __half22float2(hh[3]);
                        acc[j] += f0.x*va.x + f0.y*va.y + f1.x*va.z + f1.y*va.w
                                + f2.x*vb4.x + f2.y*vb4.y + f3.x*vb4.z + f3.y*vb4.w;
                    }
                }
                #pragma unroll
                for (int j = 0; j < 8; ++j) {
                    float s = acc[j];
                    #pragma unroll
                    for (int off = 16; off; off >>= 1)
                        s += __shfl_xor_sync(0xffffffffu, s, off);
                    if (lane == 0) {
                        int lrow = warp * 8 + j;
                        float un = INV_N / (rs_s[lrow] * s + REG);
                        u_s[lrow] = un;
                        if (it == NITER - 1) g_U[b * NP + rowbase + lrow] = un;
                    }
                }
            }
            __syncthreads();
        }
        __syncthreads();
    }
}

// ---------------------------------------------------------------------------
// v_100 = inv_n / (sum_ctab P[last parity] + eps), computed ONCE.
// grid NB, 256 threads.
// ---------------------------------------------------------------------------
__global__ void v_finalize_kernel() {
    int b = blockIdx.x;
    const int par = (NITER - 1) & 1;
    for (int i = threadIdx.x; i < NP; i += 256) {
        float s = 0.f;
        const float* P = g_P[par] + (size_t)b * CTAB * NP + i;
        #pragma unroll
        for (int sg = 0; sg < CTAB; ++sg) s += P[(size_t)sg * NP];
        g_V[b * NP + i] = INV_N / (s + REG);
    }
}

// ---------------------------------------------------------------------------
// out += sum_{b,n,m} u_n * K_nm * C_nm * v_m / B,  K_nm = Ks_nm * rowmax_n.
// Fully vectorized: one int4 of K (8 halves) + float4 y/v loads per thread.
// One block per (b, n) row; block reduce + atomicAdd.
// ---------------------------------------------------------------------------
__global__ void final_kernel(const float* __restrict__ x,
                             const float* __restrict__ y,
                             float* out) {
    int n = blockIdx.x;
    int b = blockIdx.y;
    int t = threadIdx.x;
    int m0 = t * 8;

    const float* xb = x + (size_t)b * 3 * NP;
    const float* yb = y + (size_t)b * 3 * NP;
    float x0 = xb[n], x1 = xb[NP + n], x2 = xb[2 * NP + n];

    int4 raw = ((const int4*)(g_Kh + ((size_t)(b * NP + n)) * NP))[t];
    const __half2* hh = (const __half2*)&raw;
    float2 k01 = __half22float2(hh[0]);
    float2 k23 = __half22float2(hh[1]);
    float2 k45 = __half22float2(hh[2]);
    float2 k67 = __half22float2(hh[3]);

    float4 y0a = *(const float4*)(yb + m0);
    float4 y0b = *(const float4*)(yb + m0 + 4);
    float4 y1a = *(const float4*)(yb + NP + m0);
    float4 y1b = *(const float4*)(yb + NP + m0 + 4);
    float4 y2a = *(const float4*)(yb + 2 * NP + m0);
    float4 y2b = *(const float4*)(yb + 2 * NP + m0 + 4);
    float4 v1 = *(const float4*)(g_V + b * NP + m0);
    float4 v2 = *(const float4*)(g_V + b * NP + m0 + 4);

    #define CDIST(yy0, yy1, yy2) \
        ((x0-(yy0))*(x0-(yy0)) + (x1-(yy1))*(x1-(yy1)) + (x2-(yy2))*(x2-(yy2)))
    float s =
        k01.x * CDIST(y0a.x, y1a.x, y2a.x) * v1.x +
        k01.y * CDIST(y0a.y, y1a.y, y2a.y) * v1.y +
        k23.x * CDIST(y0a.z, y1a.z, y2a.z) * v1.z +
        k23.y * CDIST(y0a.w, y1a.w, y2a.w) * v1.w +
        k45.x * CDIST(y0b.x, y1b.x, y2b.x) * v2.x +
        k45.y * CDIST(y0b.y, y1b.y, y2b.y) * v2.y +
        k67.x * CDIST(y0b.z, y1b.z, y2b.z) * v2.z +
        k67.y * CDIST(y0b.w, y1b.w, y2b.w) * v2.w;
    #undef CDIST

    __shared__ float red[256];
    red[t] = s;
    __syncthreads();
    #pragma unroll
    for (int off = 128; off; off >>= 1) {
        if (t < off) red[t] += red[t + off];
        __syncthreads();
    }
    if (t == 0) {
        float rowmax = g_RS[b * NP + n];
        atomicAdd(out, red[0] * rowmax * g_U[b * NP + n] * (1.0f / NB));
    }
}

// ---------------------------------------------------------------------------
extern "C" void kernel_launch(void* const* d_in, const int* in_sizes, int n_in,
                              void* d_out, int out_size) {
    const float* x = (const float*)d_in[0];
    const float* y = (const float*)d_in[1];
    float* out = (float*)d_out;

    init_kernel<<<(NB * NITER + 255) / 256, 256>>>(out);
    build_kernel<<<dim3(NP, NB), 256>>>(x, y);
    sinkhorn_kernel<<<NCTA, THREADS>>>();
    v_finalize_kernel<<<NB, 256>>>();
    final_kernel<<<dim3(NP, NB), 256>>>(x, y, out);
}